// round 4
// baseline (speedup 1.0000x reference)
#include <cuda_runtime.h>
#include <math.h>

typedef unsigned long long u64;

#define Cc   1024
#define C2   2048
#define Bb   32
#define Tt   1024
#define NCTA 128
#define NTHR 256

// SMEM layout (floats): sWa 32768 | arena 10240 | part 4096 | red 32
#define SM_FLOATS (32768 + 10240 + 4096 + 32)
#define SM_BYTES  (SM_FLOATS * 4)

// ------------- device scratch (static; no allocation) -------------
__device__ float  g_WaPack[(size_t)C2 * C2];        // [cta][k][16]
__device__ float  g_WbPack[(size_t)Cc * C2];        // [cta][k][8]
__device__ float  g_xT[(size_t)Bb * Tt * Cc];       // [t*C + k][r]
__device__ float  g_hT[Cc * Bb];                    // [k][r]
__device__ float  g_y1T[C2 * Bb];                   // [k][r]
__device__ float2 g_stats[NCTA * Bb];               // [cta][r] partial (sum, sumsq)
__device__ unsigned g_flags[NCTA];                  // per-CTA epoch flags

// ------------- helpers -------------
__device__ __forceinline__ u64 pk2(float a, float b) {
    u64 r; asm("mov.b64 %0,{%1,%2};" : "=l"(r) : "f"(a), "f"(b)); return r;
}
__device__ __forceinline__ void up2(u64 v, float& a, float& b) {
    asm("mov.b64 {%0,%1},%2;" : "=f"(a), "=f"(b) : "l"(v));
}
__device__ __forceinline__ void ff2(u64& d, u64 a, u64 b) {
    asm("fma.rn.f32x2 %0,%1,%2,%0;" : "+l"(d) : "l"(a), "l"(b));
}
__device__ __forceinline__ void cpa(void* s, const void* g) {
    unsigned sa = (unsigned)__cvta_generic_to_shared(s);
    asm volatile("cp.async.cg.shared.global [%0],[%1],16;" :: "r"(sa), "l"(g) : "memory");
}
__device__ __forceinline__ void cp_commit() { asm volatile("cp.async.commit_group;" ::: "memory"); }
__device__ __forceinline__ void cp_wait1()  { asm volatile("cp.async.wait_group 1;" ::: "memory"); }
__device__ __forceinline__ void cp_wait0()  { asm volatile("cp.async.wait_group 0;" ::: "memory"); }

// Multi-flag grid barrier: one release store per CTA (no atomic serialization),
// 128 parallel acquire-poll threads. Epoch is monotonic within a launch; flags
// are zeroed by prep_init each launch (stream-ordered), so graph replays are safe.
__device__ __forceinline__ void gsync(unsigned ep) {
    __syncthreads();
    if (threadIdx.x == 0) {
        asm volatile("st.release.gpu.global.u32 [%0],%1;"
                     :: "l"(&g_flags[blockIdx.x]), "r"(ep) : "memory");
    }
    if (threadIdx.x < NCTA) {
        unsigned cur;
        do {
            asm volatile("ld.acquire.gpu.global.u32 %0,[%1];"
                         : "=r"(cur) : "l"(&g_flags[threadIdx.x]) : "memory");
            if (cur < ep) __nanosleep(20);
        } while (cur < ep);
    }
    __syncthreads();
}

// ------------- prep kernels (per launch; deterministic) -------------
__global__ void prep_pack_wa(const float* __restrict__ Wa) {
    __shared__ float tile[32][33];
    int k0 = blockIdx.x * 32, j0 = blockIdx.y * 32;
    int tx = threadIdx.x & 31, ty = threadIdx.x >> 5;
    #pragma unroll
    for (int i = ty; i < 32; i += 8)
        tile[i][tx] = Wa[(size_t)(j0 + i) * C2 + k0 + tx];
    __syncthreads();
    #pragma unroll
    for (int i = ty; i < 32; i += 8) {
        int k = k0 + i, j = j0 + tx;
        g_WaPack[((size_t)(j >> 4) * C2 + k) * 16 + (j & 15)] = tile[tx][i];
    }
}

__global__ void prep_pack_wb(const float* __restrict__ Wb) {
    __shared__ float tile[32][33];
    int k0 = blockIdx.x * 32, j0 = blockIdx.y * 32;
    int tx = threadIdx.x & 31, ty = threadIdx.x >> 5;
    #pragma unroll
    for (int i = ty; i < 32; i += 8)
        tile[i][tx] = Wb[(size_t)(j0 + i) * C2 + k0 + tx];
    __syncthreads();
    #pragma unroll
    for (int i = ty; i < 32; i += 8) {
        int k = k0 + i, j = j0 + tx;
        g_WbPack[((size_t)(j >> 3) * C2 + k) * 8 + (j & 7)] = tile[tx][i];
    }
}

__global__ void prep_tr_x(const float* __restrict__ x) {
    __shared__ float tile[32][33];
    size_t m0 = (size_t)blockIdx.x * 32;
    int tx = threadIdx.x & 31, ty = threadIdx.x >> 5;
    #pragma unroll
    for (int r = ty; r < 32; r += 8)
        tile[r][tx] = x[(size_t)r * ((size_t)Tt * Cc) + m0 + tx];
    __syncthreads();
    #pragma unroll
    for (int i = ty; i < 32; i += 8)
        g_xT[(m0 + i) * Bb + tx] = tile[tx][i];
}

__global__ void prep_init() {
    int i = blockIdx.x * blockDim.x + threadIdx.x;
    if (i < Cc * Bb) g_hT[i] = 0.f;
    if (i < NCTA)    g_flags[i] = 0u;
}

// ------------- persistent recurrent kernel -------------
__global__ void __launch_bounds__(NTHR, 1)
recurrent_kernel(const float* __restrict__ ba, const float* __restrict__ bb,
                 const float* __restrict__ gamma, const float* __restrict__ beta,
                 float* __restrict__ out)
{
    extern __shared__ float smem[];
    float* sWa   = smem;              // 32768
    float* arena = smem + 32768;      // 10240
    float* part  = arena + 10240;     // 4096

    const int tid  = threadIdx.x;
    const int cta  = blockIdx.x;
    const int w    = tid >> 5;
    const int lane = tid & 31;
    const int jq   = lane >> 3;       // 0..3
    const int rq   = lane & 7;        // 0..7

    unsigned ep = 0;

    // Load this CTA's WaT slice (k-major, 16 j columns) into SMEM once.
    {
        const float4* s = (const float4*)(g_WaPack + (size_t)cta * 32768);
        float4* d = (float4*)sWa;
        #pragma unroll
        for (int i = 0; i < 32; ++i) d[tid + i * NTHR] = s[tid + i * NTHR];
    }
    __syncthreads();

    for (int t = 0; t < Tt; ++t) {
        // ================= Phase A: y1 = gelu(z @ WaT + ba) =================
        {
            float* zb0 = arena;
            float* zb1 = arena + 4096;
            {
                const float4* src = (const float4*)g_hT;
                float4* dst = (float4*)zb0;
                #pragma unroll
                for (int i = 0; i < 4; ++i) cpa(dst + tid + i * NTHR, src + tid + i * NTHR);
                cp_commit();
            }
            u64 acc[8];
            #pragma unroll
            for (int i = 0; i < 8; ++i) acc[i] = 0ULL;

            for (int tile = 0; tile < 16; ++tile) {
                float* cur = (tile & 1) ? zb1 : zb0;
                float* nxt = (tile & 1) ? zb0 : zb1;
                if (tile < 15) {
                    int ni = tile + 1;
                    const float4* src = (ni < 8)
                        ? (const float4*)(g_hT + (size_t)ni * 4096)
                        : (const float4*)(g_xT + ((size_t)t * Cc + (size_t)(ni - 8) * 128) * Bb);
                    float4* dst = (float4*)nxt;
                    #pragma unroll
                    for (int i = 0; i < 4; ++i) cpa(dst + tid + i * NTHR, src + tid + i * NTHR);
                    cp_commit();
                    cp_wait1();
                } else {
                    cp_wait0();
                }
                __syncthreads();
                const float* swab = sWa + (size_t)tile * 2048;
                #pragma unroll
                for (int kk = 0; kk < 16; ++kk) {
                    int kl = w + kk * 8;
                    ulonglong2 z01 = *(const ulonglong2*)(cur + kl * 32 + rq * 4);
                    float4 a = *(const float4*)(swab + kl * 16 + jq * 4);
                    u64 a0 = pk2(a.x, a.x), a1 = pk2(a.y, a.y);
                    u64 a2 = pk2(a.z, a.z), a3 = pk2(a.w, a.w);
                    ff2(acc[0], a0, z01.x); ff2(acc[1], a0, z01.y);
                    ff2(acc[2], a1, z01.x); ff2(acc[3], a1, z01.y);
                    ff2(acc[4], a2, z01.x); ff2(acc[5], a2, z01.y);
                    ff2(acc[6], a3, z01.x); ff2(acc[7], a3, z01.y);
                }
                __syncthreads();
            }
            // partial sums -> smem, cross-warp reduce, bias + exact GELU, emit y1T
            float* pp = part + w * 512;
            #pragma unroll
            for (int jj = 0; jj < 4; ++jj)
                #pragma unroll
                for (int p = 0; p < 2; ++p) {
                    float f0, f1; up2(acc[jj * 2 + p], f0, f1);
                    pp[(jq * 4 + jj) * 32 + rq * 4 + p * 2]     = f0;
                    pp[(jq * 4 + jj) * 32 + rq * 4 + p * 2 + 1] = f1;
                }
            __syncthreads();
            #pragma unroll
            for (int s2 = 0; s2 < 2; ++s2) {
                int idx = tid + s2 * NTHR;
                float v = 0.f;
                #pragma unroll
                for (int ww = 0; ww < 8; ++ww) v += part[ww * 512 + idx];
                int j = idx >> 5, r = idx & 31;
                v += __ldg(ba + cta * 16 + j);
                float gl = 0.5f * v * (1.0f + erff(v * 0.70710678118654752f));
                __stcg(g_y1T + (size_t)(cta * 16 + j) * 32 + r, gl);
            }
        }
        gsync(++ep);

        // ============ Phase B (+fused LayerNorm): y = y1 @ WbT + bb ============
        {
            float* yb0 = arena;
            float* yb1 = arena + 4096;
            float* wb0 = arena + 8192;
            float* wb1 = arena + 9216;
            const float* wbsrc = g_WbPack + (size_t)cta * 16384;
            {
                const float4* s1 = (const float4*)g_y1T;
                #pragma unroll
                for (int i = 0; i < 4; ++i) cpa((float4*)yb0 + tid + i * NTHR, s1 + tid + i * NTHR);
                cpa((float4*)wb0 + tid, (const float4*)wbsrc + tid);
                cp_commit();
            }
            u64 acc[4];
            #pragma unroll
            for (int i = 0; i < 4; ++i) acc[i] = 0ULL;

            for (int tile = 0; tile < 16; ++tile) {
                float* ycur = (tile & 1) ? yb1 : yb0;
                float* ynxt = (tile & 1) ? yb0 : yb1;
                float* wcur = (tile & 1) ? wb1 : wb0;
                float* wnxt = (tile & 1) ? wb0 : wb1;
                if (tile < 15) {
                    int ni = tile + 1;
                    const float4* s1 = (const float4*)(g_y1T + (size_t)ni * 4096);
                    #pragma unroll
                    for (int i = 0; i < 4; ++i) cpa((float4*)ynxt + tid + i * NTHR, s1 + tid + i * NTHR);
                    cpa((float4*)wnxt + tid, (const float4*)(wbsrc + (size_t)ni * 1024) + tid);
                    cp_commit();
                    cp_wait1();
                } else {
                    cp_wait0();
                }
                __syncthreads();
                #pragma unroll
                for (int kk = 0; kk < 16; ++kk) {
                    int kl = w + kk * 8;
                    ulonglong2 z01 = *(const ulonglong2*)(ycur + kl * 32 + rq * 4);
                    u64 wj = *(const u64*)(wcur + kl * 8 + jq * 2);
                    float w0, w1; up2(wj, w0, w1);
                    u64 s0 = pk2(w0, w0), s1v = pk2(w1, w1);
                    ff2(acc[0], s0, z01.x);  ff2(acc[1], s0, z01.y);
                    ff2(acc[2], s1v, z01.x); ff2(acc[3], s1v, z01.y);
                }
                __syncthreads();
            }
            // cross-warp reduce -> each thread owns one y value (j = tid>>5, r = tid&31)
            float* pp = part + w * 256;
            #pragma unroll
            for (int jj = 0; jj < 2; ++jj)
                #pragma unroll
                for (int p = 0; p < 2; ++p) {
                    float f0, f1; up2(acc[jj * 2 + p], f0, f1);
                    pp[(jq * 2 + jj) * 32 + rq * 4 + p * 2]     = f0;
                    pp[(jq * 2 + jj) * 32 + rq * 4 + p * 2 + 1] = f1;
                }
            __syncthreads();
            const int j = tid >> 5, r = tid & 31;
            const int k2 = cta * 8 + j;
            float v = 0.f;
            #pragma unroll
            for (int ww = 0; ww < 8; ++ww) v += part[ww * 256 + tid];
            v += __ldg(bb + k2);

            // per-CTA LN partials (sum, sumsq) over this CTA's 8 j-columns, per r
            __syncthreads();
            part[tid] = v;
            part[256 + tid] = v * v;
            __syncthreads();
            if (tid < 32) {
                float s = 0.f, q = 0.f;
                #pragma unroll
                for (int jj = 0; jj < 8; ++jj) {
                    s += part[jj * 32 + tid];
                    q += part[256 + jj * 32 + tid];
                }
                float2 st; st.x = s; st.y = q;
                __stcg(&g_stats[cta * 32 + tid], st);
            }
            gsync(++ep);

            // deterministic fixed-order reduction of all 128 CTA partials
            {
                const int grp = tid >> 5;           // 0..7, lane = r
                float ssum = 0.f, ssq = 0.f;
                #pragma unroll
                for (int c = 0; c < 16; ++c) {
                    float2 st = __ldcg(&g_stats[(grp * 16 + c) * 32 + r]);
                    ssum += st.x; ssq += st.y;
                }
                part[tid] = ssum;
                part[256 + tid] = ssq;
                __syncthreads();
                if (tid < 32) {
                    float s = 0.f, q = 0.f;
                    #pragma unroll
                    for (int g = 0; g < 8; ++g) {
                        s += part[g * 32 + tid];
                        q += part[256 + g * 32 + tid];
                    }
                    float mu  = s * (1.0f / 1024.0f);
                    float var = q * (1.0f / 1024.0f) - mu * mu;
                    part[512 + tid] = mu;
                    part[544 + tid] = rsqrtf(var + 1e-5f);
                }
                __syncthreads();
            }
            // normalize own slice, write hT (coalesced) + out (transposed via smem)
            {
                float mu = part[512 + r], rstd = part[544 + r];
                float hv = (v - mu) * rstd * __ldg(gamma + k2) + __ldg(beta + k2) + v;
                __stcg(g_hT + (size_t)k2 * 32 + r, hv);
                __syncthreads();
                part[j * 33 + r] = hv;
                __syncthreads();
                int rr = tid >> 3, jj = tid & 7;
                out[(size_t)rr * ((size_t)Tt * Cc) + (size_t)t * Cc + cta * 8 + jj]
                    = part[jj * 33 + rr];
            }
        }
        gsync(++ep);
    }
}

// ------------- host launcher -------------
extern "C" void kernel_launch(void* const* d_in, const int* in_sizes, int n_in,
                              void* d_out, int out_size) {
    const float* x     = (const float*)d_in[0];
    const float* Wa    = (const float*)d_in[1];
    const float* ba    = (const float*)d_in[2];
    const float* Wb    = (const float*)d_in[3];
    const float* bb    = (const float*)d_in[4];
    const float* gamma = (const float*)d_in[5];
    const float* beta  = (const float*)d_in[6];
    float* out = (float*)d_out;

    cudaFuncSetAttribute(recurrent_kernel,
                         cudaFuncAttributeMaxDynamicSharedMemorySize, SM_BYTES);

    prep_pack_wa<<<dim3(64, 64), 256>>>(Wa);
    prep_pack_wb<<<dim3(64, 32), 256>>>(Wb);
    prep_tr_x<<<32768, 256>>>(x);
    prep_init<<<128, 256>>>();
    recurrent_kernel<<<NCTA, NTHR, SM_BYTES>>>(ba, bb, gamma, beta, out);
}

// round 6
// speedup vs baseline: 1.6414x; 1.6414x over previous
#include <cuda_runtime.h>
#include <math.h>

typedef unsigned long long u64;

#define Cc   1024
#define C2   2048
#define Bb   32
#define Tt   1024
#define NCTA 128
#define NTHR 256

// SMEM layout (floats): sWa 32768 | arena 15360 | part 4096 | pad 32
#define SM_FLOATS (32768 + 15360 + 4096 + 32)
#define SM_BYTES  (SM_FLOATS * 4)

// ------------- device scratch (static; no allocation) -------------
__device__ float  g_WaPack[(size_t)C2 * C2];        // [cta][k][16]
__device__ float  g_WbPack[(size_t)Cc * C2];        // [cta][k][8]
__device__ float  g_xT[(size_t)Bb * Tt * Cc];       // [t*C + k][r]
__device__ float  g_hT[Cc * Bb];                    // [k][r]
__device__ float  g_y1T[C2 * Bb];                   // [k][r]
__device__ float2 g_stats[NCTA * Bb];               // [cta][r] partial (sum, sumsq)
__device__ unsigned g_arrive[NCTA];                 // per-CTA epoch flags
__device__ unsigned g_done;                         // broadcast word

// ------------- helpers -------------
__device__ __forceinline__ u64 pk2(float a, float b) {
    u64 r; asm("mov.b64 %0,{%1,%2};" : "=l"(r) : "f"(a), "f"(b)); return r;
}
__device__ __forceinline__ void up2(u64 v, float& a, float& b) {
    asm("mov.b64 {%0,%1},%2;" : "=f"(a), "=f"(b) : "l"(v));
}
__device__ __forceinline__ void ff2(u64& d, u64 a, u64 b) {
    asm("fma.rn.f32x2 %0,%1,%2,%0;" : "+l"(d) : "l"(a), "l"(b));
}
__device__ __forceinline__ void cpa(void* s, const void* g) {
    unsigned sa = (unsigned)__cvta_generic_to_shared(s);
    asm volatile("cp.async.cg.shared.global [%0],[%1],16;" :: "r"(sa), "l"(g) : "memory");
}
__device__ __forceinline__ void cp_commit() { asm volatile("cp.async.commit_group;" ::: "memory"); }
__device__ __forceinline__ void cp_wait2()  { asm volatile("cp.async.wait_group 2;" ::: "memory"); }
__device__ __forceinline__ void cp_wait1()  { asm volatile("cp.async.wait_group 1;" ::: "memory"); }
__device__ __forceinline__ void cp_wait0()  { asm volatile("cp.async.wait_group 0;" ::: "memory"); }

// Hierarchical broadcast barrier:
//  - each CTA's tid0 release-stores its own arrive flag (parallel, no atomics)
//  - CTA0's 128 threads acquire-poll the 128 flags (only 128 pollers chip-wide)
//  - CTA0 release-stores one done word; other CTAs poll it with ONE thread.
// Transitive release/acquire chain gives cross-CTA visibility.
__device__ __forceinline__ void gsync(unsigned ep) {
    __syncthreads();
    if (threadIdx.x == 0)
        asm volatile("st.release.gpu.global.u32 [%0],%1;"
                     :: "l"(g_arrive + blockIdx.x), "r"(ep) : "memory");
    if (blockIdx.x == 0) {
        if (threadIdx.x < NCTA) {
            unsigned cur;
            do {
                asm volatile("ld.acquire.gpu.global.u32 %0,[%1];"
                             : "=r"(cur) : "l"(g_arrive + threadIdx.x) : "memory");
                if (cur < ep) __nanosleep(20);
            } while (cur < ep);
        }
        __syncthreads();
        if (threadIdx.x == 0)
            asm volatile("st.release.gpu.global.u32 [%0],%1;"
                         :: "l"(&g_done), "r"(ep) : "memory");
    } else {
        if (threadIdx.x == 0) {
            unsigned cur;
            do {
                asm volatile("ld.acquire.gpu.global.u32 %0,[%1];"
                             : "=r"(cur) : "l"(&g_done) : "memory");
                if (cur < ep) __nanosleep(20);
            } while (cur < ep);
        }
    }
    __syncthreads();
}

// ------------- prep kernels (per launch; deterministic) -------------
__global__ void prep_pack_wa(const float* __restrict__ Wa) {
    __shared__ float tile[32][33];
    int k0 = blockIdx.x * 32, j0 = blockIdx.y * 32;
    int tx = threadIdx.x & 31, ty = threadIdx.x >> 5;
    #pragma unroll
    for (int i = ty; i < 32; i += 8)
        tile[i][tx] = Wa[(size_t)(j0 + i) * C2 + k0 + tx];
    __syncthreads();
    #pragma unroll
    for (int i = ty; i < 32; i += 8) {
        int k = k0 + i, j = j0 + tx;
        g_WaPack[((size_t)(j >> 4) * C2 + k) * 16 + (j & 15)] = tile[tx][i];
    }
}

__global__ void prep_pack_wb(const float* __restrict__ Wb) {
    __shared__ float tile[32][33];
    int k0 = blockIdx.x * 32, j0 = blockIdx.y * 32;
    int tx = threadIdx.x & 31, ty = threadIdx.x >> 5;
    #pragma unroll
    for (int i = ty; i < 32; i += 8)
        tile[i][tx] = Wb[(size_t)(j0 + i) * C2 + k0 + tx];
    __syncthreads();
    #pragma unroll
    for (int i = ty; i < 32; i += 8) {
        int k = k0 + i, j = j0 + tx;
        g_WbPack[((size_t)(j >> 3) * C2 + k) * 8 + (j & 7)] = tile[tx][i];
    }
}

__global__ void prep_tr_x(const float* __restrict__ x) {
    __shared__ float tile[32][33];
    size_t m0 = (size_t)blockIdx.x * 32;
    int tx = threadIdx.x & 31, ty = threadIdx.x >> 5;
    #pragma unroll
    for (int r = ty; r < 32; r += 8)
        tile[r][tx] = x[(size_t)r * ((size_t)Tt * Cc) + m0 + tx];
    __syncthreads();
    #pragma unroll
    for (int i = ty; i < 32; i += 8)
        g_xT[(m0 + i) * Bb + tx] = tile[tx][i];
}

__global__ void prep_init() {
    int i = blockIdx.x * blockDim.x + threadIdx.x;
    if (i < Cc * Bb) g_hT[i] = 0.f;
    if (i < NCTA)    g_arrive[i] = 0u;
    if (i == 0)      g_done = 0u;
}

// ------------- persistent recurrent kernel -------------
__global__ void __launch_bounds__(NTHR, 1)
recurrent_kernel(const float* __restrict__ ba, const float* __restrict__ bb,
                 const float* __restrict__ gamma, const float* __restrict__ beta,
                 float* __restrict__ out)
{
    extern __shared__ float smem[];
    float* sWa   = smem;              // 32768
    float* arena = smem + 32768;      // 15360
    float* part  = arena + 15360;     // 4096

    const int tid  = threadIdx.x;
    const int cta  = blockIdx.x;
    const int w    = tid >> 5;
    const int lane = tid & 31;
    const int jq   = lane >> 3;       // 0..3
    const int rq   = lane & 7;        // 0..7

    unsigned ep = 0;

    // Load this CTA's WaT slice (k-major, 16 j columns) into SMEM once.
    {
        const float4* s = (const float4*)(g_WaPack + (size_t)cta * 32768);
        float4* d = (float4*)sWa;
        #pragma unroll
        for (int i = 0; i < 32; ++i) d[tid + i * NTHR] = s[tid + i * NTHR];
    }
    __syncthreads();

    for (int t = 0; t < Tt; ++t) {
        // ================= Phase A: y1 = gelu(z @ WaT + ba) =================
        {
            auto zsrc = [&](int ni) -> const float4* {
                return (ni < 8)
                    ? (const float4*)(g_hT + (size_t)ni * 4096)
                    : (const float4*)(g_xT + ((size_t)t * Cc + (size_t)(ni - 8) * 128) * Bb);
            };
            #pragma unroll
            for (int pf = 0; pf < 2; ++pf) {
                float4* dst = (float4*)(arena + pf * 4096);
                const float4* src = zsrc(pf);
                #pragma unroll
                for (int i = 0; i < 4; ++i) cpa(dst + tid + i * NTHR, src + tid + i * NTHR);
                cp_commit();
            }
            u64 acc[8];
            #pragma unroll
            for (int i = 0; i < 8; ++i) acc[i] = 0ULL;

            for (int tile = 0; tile < 16; ++tile) {
                float* cur = arena + (tile % 3) * 4096;
                if (tile + 2 < 16) {
                    float* nxt = arena + ((tile + 2) % 3) * 4096;
                    const float4* src = zsrc(tile + 2);
                    float4* dst = (float4*)nxt;
                    #pragma unroll
                    for (int i = 0; i < 4; ++i) cpa(dst + tid + i * NTHR, src + tid + i * NTHR);
                    cp_commit();
                    cp_wait2();
                } else if (tile + 1 < 16) {
                    cp_wait1();
                } else {
                    cp_wait0();
                }
                __syncthreads();
                const float* swab = sWa + (size_t)tile * 2048;
                #pragma unroll
                for (int kk = 0; kk < 16; ++kk) {
                    int kl = w + kk * 8;
                    ulonglong2 z01 = *(const ulonglong2*)(cur + kl * 32 + rq * 4);
                    float4 a = *(const float4*)(swab + kl * 16 + jq * 4);
                    u64 a0 = pk2(a.x, a.x), a1 = pk2(a.y, a.y);
                    u64 a2 = pk2(a.z, a.z), a3 = pk2(a.w, a.w);
                    ff2(acc[0], a0, z01.x); ff2(acc[1], a0, z01.y);
                    ff2(acc[2], a1, z01.x); ff2(acc[3], a1, z01.y);
                    ff2(acc[4], a2, z01.x); ff2(acc[5], a2, z01.y);
                    ff2(acc[6], a3, z01.x); ff2(acc[7], a3, z01.y);
                }
                __syncthreads();
            }
            // partial sums -> smem, cross-warp reduce, bias + exact GELU, emit y1T
            float* pp = part + w * 512;
            #pragma unroll
            for (int jj = 0; jj < 4; ++jj)
                #pragma unroll
                for (int p = 0; p < 2; ++p) {
                    float f0, f1; up2(acc[jj * 2 + p], f0, f1);
                    pp[(jq * 4 + jj) * 32 + rq * 4 + p * 2]     = f0;
                    pp[(jq * 4 + jj) * 32 + rq * 4 + p * 2 + 1] = f1;
                }
            __syncthreads();
            #pragma unroll
            for (int s2 = 0; s2 < 2; ++s2) {
                int idx = tid + s2 * NTHR;
                float v = 0.f;
                #pragma unroll
                for (int ww = 0; ww < 8; ++ww) v += part[ww * 512 + idx];
                int j = idx >> 5, r = idx & 31;
                v += __ldg(ba + cta * 16 + j);
                float gl = 0.5f * v * (1.0f + erff(v * 0.70710678118654752f));
                __stcg(g_y1T + (size_t)(cta * 16 + j) * 32 + r, gl);
            }
        }
        gsync(++ep);

        // ============ Phase B (+fused LayerNorm): y = y1 @ WbT + bb ============
        {
            float* ybase = arena;
            float* wbase = arena + 12288;
            const float* wbsrc = g_WbPack + (size_t)cta * 16384;
            #pragma unroll
            for (int pf = 0; pf < 2; ++pf) {
                const float4* s1 = (const float4*)(g_y1T + (size_t)pf * 4096);
                float4* yd = (float4*)(ybase + pf * 4096);
                #pragma unroll
                for (int i = 0; i < 4; ++i) cpa(yd + tid + i * NTHR, s1 + tid + i * NTHR);
                cpa((float4*)(wbase + pf * 1024) + tid, (const float4*)(wbsrc + (size_t)pf * 1024) + tid);
                cp_commit();
            }
            u64 acc[4];
            #pragma unroll
            for (int i = 0; i < 4; ++i) acc[i] = 0ULL;

            for (int tile = 0; tile < 16; ++tile) {
                float* ycur = ybase + (tile % 3) * 4096;
                float* wcur = wbase + (tile % 3) * 1024;
                if (tile + 2 < 16) {
                    int ni = tile + 2;
                    const float4* s1 = (const float4*)(g_y1T + (size_t)ni * 4096);
                    float4* yd = (float4*)(ybase + (ni % 3) * 4096);
                    #pragma unroll
                    for (int i = 0; i < 4; ++i) cpa(yd + tid + i * NTHR, s1 + tid + i * NTHR);
                    cpa((float4*)(wbase + (ni % 3) * 1024) + tid,
                        (const float4*)(wbsrc + (size_t)ni * 1024) + tid);
                    cp_commit();
                    cp_wait2();
                } else if (tile + 1 < 16) {
                    cp_wait1();
                } else {
                    cp_wait0();
                }
                __syncthreads();
                #pragma unroll
                for (int kk = 0; kk < 16; ++kk) {
                    int kl = w + kk * 8;
                    ulonglong2 z01 = *(const ulonglong2*)(ycur + kl * 32 + rq * 4);
                    u64 wj = *(const u64*)(wcur + kl * 8 + jq * 2);
                    float w0, w1; up2(wj, w0, w1);
                    u64 s0 = pk2(w0, w0), s1v = pk2(w1, w1);
                    ff2(acc[0], s0, z01.x);  ff2(acc[1], s0, z01.y);
                    ff2(acc[2], s1v, z01.x); ff2(acc[3], s1v, z01.y);
                }
                __syncthreads();
            }
            // cross-warp reduce -> each thread owns one y value (j = tid>>5, r = tid&31)
            float* pp = part + w * 256;
            #pragma unroll
            for (int jj = 0; jj < 2; ++jj)
                #pragma unroll
                for (int p = 0; p < 2; ++p) {
                    float f0, f1; up2(acc[jj * 2 + p], f0, f1);
                    pp[(jq * 2 + jj) * 32 + rq * 4 + p * 2]     = f0;
                    pp[(jq * 2 + jj) * 32 + rq * 4 + p * 2 + 1] = f1;
                }
            __syncthreads();
            const int j = tid >> 5, r = tid & 31;
            const int k2 = cta * 8 + j;
            float v = 0.f;
            #pragma unroll
            for (int ww = 0; ww < 8; ++ww) v += part[ww * 256 + tid];
            v += __ldg(bb + k2);

            // per-CTA LN partials (sum, sumsq) over this CTA's 8 j-columns, per r
            __syncthreads();
            part[tid] = v;
            part[256 + tid] = v * v;
            __syncthreads();
            if (tid < 32) {
                float s = 0.f, q = 0.f;
                #pragma unroll
                for (int jj = 0; jj < 8; ++jj) {
                    s += part[jj * 32 + tid];
                    q += part[256 + jj * 32 + tid];
                }
                float2 st; st.x = s; st.y = q;
                __stcg(&g_stats[cta * 32 + tid], st);
            }
            gsync(++ep);

            // deterministic fixed-order reduction of all 128 CTA partials
            {
                const int grp = tid >> 5;           // 0..7, lane = r
                float ssum = 0.f, ssq = 0.f;
                #pragma unroll
                for (int c = 0; c < 16; ++c) {
                    float2 st = __ldcg(&g_stats[(grp * 16 + c) * 32 + r]);
                    ssum += st.x; ssq += st.y;
                }
                part[tid] = ssum;
                part[256 + tid] = ssq;
                __syncthreads();
                if (tid < 32) {
                    float s = 0.f, q = 0.f;
                    #pragma unroll
                    for (int g = 0; g < 8; ++g) {
                        s += part[g * 32 + tid];
                        q += part[256 + g * 32 + tid];
                    }
                    float mu  = s * (1.0f / 1024.0f);
                    float var = q * (1.0f / 1024.0f) - mu * mu;
                    part[512 + tid] = mu;
                    part[544 + tid] = rsqrtf(var + 1e-5f);
                }
                __syncthreads();
            }
            // normalize own slice, write hT (coalesced) + out (transposed via smem)
            {
                float mu = part[512 + r], rstd = part[544 + r];
                float hv = (v - mu) * rstd * __ldg(gamma + k2) + __ldg(beta + k2) + v;
                __stcg(g_hT + (size_t)k2 * 32 + r, hv);
                __syncthreads();
                part[j * 33 + r] = hv;
                __syncthreads();
                int rr = tid >> 3, jj = tid & 7;
                out[(size_t)rr * ((size_t)Tt * Cc) + (size_t)t * Cc + cta * 8 + jj]
                    = part[jj * 33 + rr];
            }
        }
        gsync(++ep);
    }
}

// ------------- host launcher -------------
extern "C" void kernel_launch(void* const* d_in, const int* in_sizes, int n_in,
                              void* d_out, int out_size) {
    const float* x     = (const float*)d_in[0];
    const float* Wa    = (const float*)d_in[1];
    const float* ba    = (const float*)d_in[2];
    const float* Wb    = (const float*)d_in[3];
    const float* bb    = (const float*)d_in[4];
    const float* gamma = (const float*)d_in[5];
    const float* beta  = (const float*)d_in[6];
    float* out = (float*)d_out;

    cudaFuncSetAttribute(recurrent_kernel,
                         cudaFuncAttributeMaxDynamicSharedMemorySize, SM_BYTES);

    prep_pack_wa<<<dim3(64, 64), 256>>>(Wa);
    prep_pack_wb<<<dim3(64, 32), 256>>>(Wb);
    prep_tr_x<<<32768, 256>>>(x);
    prep_init<<<128, 256>>>();
    recurrent_kernel<<<NCTA, NTHR, SM_BYTES>>>(ba, bb, gamma, beta, out);
}